// round 3
// baseline (speedup 1.0000x reference)
#include <cuda_runtime.h>
#include <stdint.h>

#define BB 4
#define NP 8192
#define NG 8192
#define T  256         // threads per block
#define Q  8           // queries per thread
#define SL 8           // slices per direction (y-dim)
#define TILE 1024      // tile points (16 KB smem)
#define GRID_X (NP / (T * Q))   // 4
#define NBLK (GRID_X * SL * 2 * BB)  // 256 total blocks

#define INF_BITS 0x7F800000u

// ---------------- device scratch (no allocs allowed) ----------------
__device__ float    g_gt[BB][3][NG];   // compacted valid gt, SoA (sentinel coords = 0)
__device__ float    g_gtsq[BB][NG];    // |g|^2 per compacted gt (sentinel = +inf)
__device__ int      g_gtidx[BB][NG];   // original gt index of compacted entry
__device__ int      g_cnt[BB];
__device__ unsigned g_prmin[BB * NP];  // per-pred min d2 (float bits)
__device__ unsigned g_gtmin[BB * NG];  // per-ORIGINAL-gt min d2 (float bits)
__device__ int      g_fmt;             // 1 = gt_valid int32, 0 = 1-byte bool
__device__ int      g_done;            // completion counter (reset each replay)

// ---------------- packed f32x2 helpers ----------------
__device__ __forceinline__ unsigned long long f2pk(float lo, float hi) {
    unsigned long long r;
    asm("mov.b64 %0, {%1,%2};" : "=l"(r) : "f"(lo), "f"(hi));
    return r;
}
__device__ __forceinline__ unsigned long long fma2(unsigned long long a, unsigned long long b,
                                                   unsigned long long c) {
    unsigned long long r;
    asm("fma.rn.f32x2 %0, %1, %2, %3;" : "=l"(r) : "l"(a), "l"(b), "l"(c));
    return r;
}
__device__ __forceinline__ void upk(unsigned long long v, float& lo, float& hi) {
    asm("mov.b64 {%0,%1}, %2;" : "=f"(lo), "=f"(hi) : "l"(v));
}

// ---------------- kernels ----------------
// init scratch + detect gt_valid format (any 32-bit word > 1 => byte-bool).
__global__ void k_init(const unsigned* __restrict__ w) {
    int stride = gridDim.x * blockDim.x;
    int i = blockIdx.x * blockDim.x + threadIdx.x;
    float* gtf = &g_gt[0][0][0];
    for (int k = i; k < BB * 3 * NG; k += stride) gtf[k] = 0.f;           // sentinel coords
    float* sqf = &g_gtsq[0][0];
    for (int k = i; k < BB * NG; k += stride) sqf[k] = __int_as_float(INF_BITS);
    for (int k = i; k < BB * NP; k += stride) g_prmin[k] = INF_BITS;
    for (int k = i; k < BB * NG; k += stride) g_gtmin[k] = INF_BITS;
    if (i < BB) g_cnt[i] = 0;
    if (i == 0) { g_fmt = 1; g_done = 0; }
    // detect: safe to read (BB*NG)/4 words under both layouts
    for (int k = i; k < (BB * NG) / 4; k += stride)
        if (w[k] > 1u) g_fmt = 0;
}

__global__ void k_compact(const float* __restrict__ gt, const void* __restrict__ valid) {
    int i = blockIdx.x * blockDim.x + threadIdx.x;
    if (i >= BB * NG) return;
    int b = i / NG, g = i % NG;
    bool v;
    if (g_fmt)
        v = (reinterpret_cast<const int*>(valid)[i] != 0);
    else
        v = (reinterpret_cast<const unsigned char*>(valid)[i] != 0);
    if (v) {
        int p = atomicAdd(&g_cnt[b], 1);
        const float* s = gt + (size_t)i * 3;
        float x = s[0], y = s[1], z = s[2];
        g_gt[b][0][p] = x;
        g_gt[b][1][p] = y;
        g_gt[b][2][p] = z;
        g_gtsq[b][p]  = x * x + y * y + z * z;
        g_gtidx[b][p] = g;
    }
}

// Fused bidirectional Chamfer + last-block final reduction.
// blockIdx.z in [0, 2*BB): z < BB -> accuracy (queries = pred, tile = gt)
//                          z >= BB -> completeness (queries = compacted gt, tile = pred)
// Tile pair-SoA: s[2k]=(x0,x1,y0,y1), s[2k+1]=(z0,z1,sq0,sq1).
// t = fma2(-2qx,gx, fma2(-2qy,gy, fma2(-2qz,gz, gsq))); result = min(t) + |q|^2.
__global__ void __launch_bounds__(T, 2) k_cd(const float* __restrict__ pr,
                                             float* __restrict__ out) {
    int zz = blockIdx.z;
    int b = zz & (BB - 1);
    bool is_acc = zz < BB;
    int cnt = g_cnt[b];

    __shared__ __align__(16) float4 s[TILE];  // 16 KB

    int qbase = blockIdx.x * (T * Q);
    bool active;
    int tileLen = 0, t0 = 0;
    if (is_acc) {
        int npad = (cnt + 7) & ~7;
        int L = (((npad + SL - 1) / SL) + 7) & ~7;   // slice len, mult of 8, <= TILE
        t0 = blockIdx.y * L;
        int t1 = min(t0 + L, npad);
        active = (t0 < t1);
        tileLen = active ? (t1 - t0) : 0;
    } else {
        t0 = blockIdx.y * (NP / SL);
        tileLen = NP / SL;   // 1024
        active = (qbase < cnt);
    }

    if (active) {
        if (is_acc) {
            for (int i = threadIdx.x; i < tileLen; i += T) {
                float x = g_gt[b][0][t0 + i];
                float y = g_gt[b][1][t0 + i];
                float z = g_gt[b][2][t0 + i];
                float sq = g_gtsq[b][t0 + i];
                float* base = reinterpret_cast<float*>(&s[(i >> 1) * 2]);
                int h = i & 1;
                base[0 + h] = x; base[2 + h] = y; base[4 + h] = z; base[6 + h] = sq;
            }
        } else {
            for (int i = threadIdx.x; i < tileLen; i += T) {
                const float* p = pr + ((size_t)b * NP + t0 + i) * 3;
                float x = p[0], y = p[1], z = p[2];
                float sq = x * x + y * y + z * z;
                float* base = reinterpret_cast<float*>(&s[(i >> 1) * 2]);
                int h = i & 1;
                base[0 + h] = x; base[2 + h] = y; base[4 + h] = z; base[6 + h] = sq;
            }
        }
        __syncthreads();

        unsigned long long q2x[Q], q2y[Q], q2z[Q];
        float qsq[Q], m0[Q], m1[Q];
#pragma unroll
        for (int q = 0; q < Q; q++) {
            int qq = qbase + threadIdx.x + q * T;
            float x, y, z, sq;
            if (is_acc) {
                const float* p = pr + ((size_t)b * NP + qq) * 3;
                x = p[0]; y = p[1]; z = p[2];
                sq = x * x + y * y + z * z;
            } else {
                x = g_gt[b][0][qq]; y = g_gt[b][1][qq]; z = g_gt[b][2][qq];
                sq = (qq < cnt) ? g_gtsq[b][qq] : 0.f;
            }
            float nx = -2.f * x, ny = -2.f * y, nz = -2.f * z;
            q2x[q] = f2pk(nx, nx); q2y[q] = f2pk(ny, ny); q2z[q] = f2pk(nz, nz);
            qsq[q] = sq;
            m0[q] = __uint_as_float(INF_BITS);
            m1[q] = __uint_as_float(INF_BITS);
        }

        int pairs = tileLen >> 1;
#pragma unroll 2
        for (int k = 0; k < pairs; k++) {
            float4 a  = s[k * 2];
            float4 bv = s[k * 2 + 1];
            unsigned long long gx = f2pk(a.x, a.y);
            unsigned long long gy = f2pk(a.z, a.w);
            unsigned long long gz = f2pk(bv.x, bv.y);
            unsigned long long gs = f2pk(bv.z, bv.w);
#pragma unroll
            for (int q = 0; q < Q; q++) {
                unsigned long long t = fma2(q2x[q], gx, fma2(q2y[q], gy, fma2(q2z[q], gz, gs)));
                float tl, th; upk(t, tl, th);
                m0[q] = fminf(m0[q], tl);
                m1[q] = fminf(m1[q], th);
            }
        }

#pragma unroll
        for (int q = 0; q < Q; q++) {
            int qq = qbase + threadIdx.x + q * T;
            float m = fmaxf(fminf(m0[q], m1[q]) + qsq[q], 0.f);
            if (is_acc) {
                atomicMin(&g_prmin[b * NP + qq], __float_as_uint(m));
            } else if (qq < cnt) {
                int orig = g_gtidx[b][qq];
                atomicMin(&g_gtmin[b * NG + orig], __float_as_uint(m));
            }
        }
    }

    // ---- completion: last block does the final reduction ----
    __shared__ bool isLast;
    __shared__ float sa;
    __shared__ float sc[BB];
    __threadfence();
    __syncthreads();
    if (threadIdx.x == 0) {
        int prev = atomicAdd(&g_done, 1);
        isLast = (prev == NBLK - 1);
        if (isLast) __threadfence();   // acquire all blocks' writes
        sa = 0.f;
    }
    if (threadIdx.x < BB) sc[threadIdx.x] = 0.f;
    __syncthreads();
    if (!isLast) return;

    float la = 0.f;
    for (int i = threadIdx.x; i < BB * NP; i += T)
        la += __uint_as_float(g_prmin[i]);
    atomicAdd(&sa, la);

    for (int bb = 0; bb < BB; bb++) {
        float lc = 0.f;
        for (int i = threadIdx.x; i < NG; i += T) {
            unsigned v = g_gtmin[bb * NG + i];
            if (v != INF_BITS) lc += __uint_as_float(v);  // only valid gt were written
        }
        atomicAdd(&sc[bb], lc);
    }
    __syncthreads();

    if (threadIdx.x == 0) {
        float loss_acc = sa / (float)(BB * NP);
        float loss_com = 0.f;
        for (int bb = 0; bb < BB; bb++)
            loss_com += sc[bb] / fmaxf((float)g_cnt[bb], 1.f);
        loss_com /= (float)BB;
        out[0] = 2.f * (loss_acc + loss_com);  // acc + com + cd, cd = acc + com
        g_done = 0;                            // reset for next graph replay
    }
}

// ---------------- launch ----------------
extern "C" void kernel_launch(void* const* d_in, const int* in_sizes, int n_in,
                              void* d_out, int out_size) {
    const float* pr    = (const float*)d_in[0];  // [B,NP,3] f32
    const float* gt    = (const float*)d_in[1];  // [B,NG,3] f32
    const void*  valid = d_in[2];                // [B,NG] bool(1B) or int32

    k_init<<<256, 256>>>((const unsigned*)valid);
    k_compact<<<(BB * NG + 255) / 256, 256>>>(gt, valid);
    k_cd<<<dim3(GRID_X, SL, 2 * BB), T>>>(pr, (float*)d_out);
}

// round 4
// speedup vs baseline: 1.2917x; 1.2917x over previous
#include <cuda_runtime.h>
#include <stdint.h>

#define BB 4
#define NP 8192
#define NG 8192
#define T  256        // threads per block
#define Q  4          // queries per thread
#define GS 16         // gt slices (acc direction)
#define PS 16         // pred slices (com direction)
#define PSL (NP / PS) // 512 pred points per slice
#define GRID_X (NP / (T * Q))          // 8
#define NBLK (GRID_X * GS * 2 * BB)    // 1024 blocks

#define INF_BITS 0x7F800000u

// ---------------- device scratch (no allocs allowed) ----------------
__device__ float    g_gt[BB][3][NG];   // compacted valid gt, SoA (sentinel coords = 0)
__device__ float    g_gtsq[BB][NG];    // |g|^2 per compacted gt (sentinel = +inf)
__device__ int      g_gtidx[BB][NG];   // original gt index of compacted entry
__device__ int      g_cnt[BB];
__device__ unsigned g_prmin[BB * NP];  // per-pred min d2 (float bits)
__device__ unsigned g_gtmin[BB * NG];  // per-ORIGINAL-gt min d2 (float bits)
__device__ int      g_fmt;             // 1 = gt_valid int32, 0 = 1-byte bool
__device__ int      g_done;            // completion counter (reset each replay)

// ---------------- packed f32x2 helpers ----------------
__device__ __forceinline__ unsigned long long f2pk(float lo, float hi) {
    unsigned long long r;
    asm("mov.b64 %0, {%1,%2};" : "=l"(r) : "f"(lo), "f"(hi));
    return r;
}
__device__ __forceinline__ unsigned long long fma2(unsigned long long a, unsigned long long b,
                                                   unsigned long long c) {
    unsigned long long r;
    asm("fma.rn.f32x2 %0, %1, %2, %3;" : "=l"(r) : "l"(a), "l"(b), "l"(c));
    return r;
}
__device__ __forceinline__ void upk(unsigned long long v, float& lo, float& hi) {
    asm("mov.b64 {%0,%1}, %2;" : "=f"(lo), "=f"(hi) : "l"(v));
}

// ---------------- kernels ----------------
// init scratch + detect gt_valid format (any 32-bit word > 1 => byte-bool).
__global__ void k_init(const unsigned* __restrict__ w) {
    int stride = gridDim.x * blockDim.x;
    int i = blockIdx.x * blockDim.x + threadIdx.x;
    float* gtf = &g_gt[0][0][0];
    for (int k = i; k < BB * 3 * NG; k += stride) gtf[k] = 0.f;           // sentinel coords
    float* sqf = &g_gtsq[0][0];
    for (int k = i; k < BB * NG; k += stride) sqf[k] = __int_as_float(INF_BITS);
    for (int k = i; k < BB * NP; k += stride) g_prmin[k] = INF_BITS;
    for (int k = i; k < BB * NG; k += stride) g_gtmin[k] = INF_BITS;
    if (i < BB) g_cnt[i] = 0;
    if (i == 0) { g_fmt = 1; g_done = 0; }
    // detect: safe to read (BB*NG)/4 words under both layouts
    for (int k = i; k < (BB * NG) / 4; k += stride)
        if (w[k] > 1u) g_fmt = 0;
}

__global__ void k_compact(const float* __restrict__ gt, const void* __restrict__ valid) {
    int i = blockIdx.x * blockDim.x + threadIdx.x;
    if (i >= BB * NG) return;
    int b = i / NG, g = i % NG;
    bool v;
    if (g_fmt)
        v = (reinterpret_cast<const int*>(valid)[i] != 0);
    else
        v = (reinterpret_cast<const unsigned char*>(valid)[i] != 0);
    if (v) {
        int p = atomicAdd(&g_cnt[b], 1);
        const float* s = gt + (size_t)i * 3;
        float x = s[0], y = s[1], z = s[2];
        g_gt[b][0][p] = x;
        g_gt[b][1][p] = y;
        g_gt[b][2][p] = z;
        g_gtsq[b][p]  = x * x + y * y + z * z;
        g_gtidx[b][p] = g;
    }
}

// Fused bidirectional Chamfer + last-block final reduction.
// blockIdx.z in [0, 2*BB): z < BB -> accuracy (queries = pred, tile = gt)
//                          z >= BB -> completeness (queries = compacted gt, tile = pred)
// Tile pair-SoA: s[2k]=(x0,x1,y0,y1), s[2k+1]=(z0,z1,sq0,sq1).
// t = fma2(-2qx,gx, fma2(-2qy,gy, fma2(-2qz,gz, gsq))); result = min(t) + |q|^2.
__global__ void __launch_bounds__(T) k_cd(const float* __restrict__ pr,
                                          float* __restrict__ out) {
    int zz = blockIdx.z;
    int b = zz & (BB - 1);
    bool is_acc = zz < BB;
    int cnt = g_cnt[b];

    __shared__ __align__(16) float4 s[PSL];  // 8 KB (512 points)

    int qbase = blockIdx.x * (T * Q);
    bool active;
    int tileLen = 0, t0 = 0;
    if (is_acc) {
        int npad = (cnt + 7) & ~7;
        int L = (((npad + GS - 1) / GS) + 7) & ~7;   // slice len, mult of 8, <= 512
        t0 = blockIdx.y * L;
        int t1 = min(t0 + L, npad);
        active = (t0 < t1);
        tileLen = active ? (t1 - t0) : 0;
    } else {
        t0 = blockIdx.y * PSL;
        tileLen = PSL;
        active = (qbase < cnt);
    }

    if (active) {
        if (is_acc) {
            for (int i = threadIdx.x; i < tileLen; i += T) {
                float x = g_gt[b][0][t0 + i];
                float y = g_gt[b][1][t0 + i];
                float z = g_gt[b][2][t0 + i];
                float sq = g_gtsq[b][t0 + i];
                float* base = reinterpret_cast<float*>(&s[(i >> 1) * 2]);
                int h = i & 1;
                base[0 + h] = x; base[2 + h] = y; base[4 + h] = z; base[6 + h] = sq;
            }
        } else {
            for (int i = threadIdx.x; i < tileLen; i += T) {
                const float* p = pr + ((size_t)b * NP + t0 + i) * 3;
                float x = p[0], y = p[1], z = p[2];
                float sq = x * x + y * y + z * z;
                float* base = reinterpret_cast<float*>(&s[(i >> 1) * 2]);
                int h = i & 1;
                base[0 + h] = x; base[2 + h] = y; base[4 + h] = z; base[6 + h] = sq;
            }
        }
        __syncthreads();

        unsigned long long q2x[Q], q2y[Q], q2z[Q];
        float qsq[Q], m0[Q], m1[Q];
#pragma unroll
        for (int q = 0; q < Q; q++) {
            int qq = qbase + threadIdx.x + q * T;
            float x, y, z, sq;
            if (is_acc) {
                const float* p = pr + ((size_t)b * NP + qq) * 3;
                x = p[0]; y = p[1]; z = p[2];
                sq = x * x + y * y + z * z;
            } else {
                x = g_gt[b][0][qq]; y = g_gt[b][1][qq]; z = g_gt[b][2][qq];
                sq = (qq < cnt) ? g_gtsq[b][qq] : 0.f;
            }
            float nx = -2.f * x, ny = -2.f * y, nz = -2.f * z;
            q2x[q] = f2pk(nx, nx); q2y[q] = f2pk(ny, ny); q2z[q] = f2pk(nz, nz);
            qsq[q] = sq;
            m0[q] = __uint_as_float(INF_BITS);
            m1[q] = __uint_as_float(INF_BITS);
        }

        int pairs = tileLen >> 1;
#pragma unroll 4
        for (int k = 0; k < pairs; k++) {
            float4 a  = s[k * 2];
            float4 bv = s[k * 2 + 1];
            unsigned long long gx = f2pk(a.x, a.y);
            unsigned long long gy = f2pk(a.z, a.w);
            unsigned long long gz = f2pk(bv.x, bv.y);
            unsigned long long gs = f2pk(bv.z, bv.w);
#pragma unroll
            for (int q = 0; q < Q; q++) {
                unsigned long long t = fma2(q2x[q], gx, fma2(q2y[q], gy, fma2(q2z[q], gz, gs)));
                float tl, th; upk(t, tl, th);
                m0[q] = fminf(m0[q], tl);
                m1[q] = fminf(m1[q], th);
            }
        }

#pragma unroll
        for (int q = 0; q < Q; q++) {
            int qq = qbase + threadIdx.x + q * T;
            float m = fmaxf(fminf(m0[q], m1[q]) + qsq[q], 0.f);
            if (is_acc) {
                atomicMin(&g_prmin[b * NP + qq], __float_as_uint(m));
            } else if (qq < cnt) {
                int orig = g_gtidx[b][qq];
                atomicMin(&g_gtmin[b * NG + orig], __float_as_uint(m));
            }
        }
    }

    // ---- completion: last block does the final reduction ----
    __shared__ bool isLast;
    __shared__ float sa;
    __shared__ float sc[BB];
    __threadfence();
    __syncthreads();
    if (threadIdx.x == 0) {
        int prev = atomicAdd(&g_done, 1);
        isLast = (prev == NBLK - 1);
        if (isLast) __threadfence();   // acquire all blocks' writes
        sa = 0.f;
    }
    if (threadIdx.x < BB) sc[threadIdx.x] = 0.f;
    __syncthreads();
    if (!isLast) return;

    float la = 0.f;
    for (int i = threadIdx.x; i < BB * NP; i += T)
        la += __uint_as_float(g_prmin[i]);
    atomicAdd(&sa, la);

    for (int bb = 0; bb < BB; bb++) {
        float lc = 0.f;
        for (int i = threadIdx.x; i < NG; i += T) {
            unsigned v = g_gtmin[bb * NG + i];
            if (v != INF_BITS) lc += __uint_as_float(v);  // only valid gt were written
        }
        atomicAdd(&sc[bb], lc);
    }
    __syncthreads();

    if (threadIdx.x == 0) {
        float loss_acc = sa / (float)(BB * NP);
        float loss_com = 0.f;
        for (int bb = 0; bb < BB; bb++)
            loss_com += sc[bb] / fmaxf((float)g_cnt[bb], 1.f);
        loss_com /= (float)BB;
        out[0] = 2.f * (loss_acc + loss_com);  // acc + com + cd, cd = acc + com
        g_done = 0;                            // reset for next graph replay
    }
}

// ---------------- launch ----------------
extern "C" void kernel_launch(void* const* d_in, const int* in_sizes, int n_in,
                              void* d_out, int out_size) {
    const float* pr    = (const float*)d_in[0];  // [B,NP,3] f32
    const float* gt    = (const float*)d_in[1];  // [B,NG,3] f32
    const void*  valid = d_in[2];                // [B,NG] bool(1B) or int32

    k_init<<<256, 256>>>((const unsigned*)valid);
    k_compact<<<(BB * NG + 255) / 256, 256>>>(gt, valid);
    k_cd<<<dim3(GRID_X, GS, 2 * BB), T>>>(pr, (float*)d_out);
}

// round 5
// speedup vs baseline: 1.3768x; 1.0658x over previous
#include <cuda_runtime.h>
#include <stdint.h>

#define BB 4
#define NP 8192
#define NG 8192
#define T  256          // threads per block
#define Q  4            // queries per thread
#define SLA 8           // gt slices (acc direction)  -> L ~ cnt/8 (~512)
#define PS 16           // pred slices (com direction)
#define PSL (NP / PS)   // 512 pred points per slice
#define GRID_X (NP / (T * Q))           // 8
#define GRID_Z (SLA * BB + PS * BB)     // 32 + 64 = 96
#define NBLK (GRID_X * GRID_Z)          // 768 blocks
#define TILE_MAX 1024                   // max points per tile (16 KB smem)

#define INF_BITS 0x7F800000u

// ---------------- device scratch (no allocs allowed) ----------------
__device__ float    g_gt[BB][3][NG];   // compacted valid gt, SoA ([cnt,NG) = stale/garbage, never used)
__device__ float    g_gtsq[BB][NG];    // |g|^2 per compacted gt
__device__ int      g_gtidx[BB][NG];   // original gt index of compacted entry
__device__ int      g_cnt[BB];
__device__ unsigned g_prmin[BB * NP];  // per-pred min d2 (float bits)
__device__ unsigned g_gtmin[BB * NG];  // per-ORIGINAL-gt min d2 (float bits)
__device__ int      g_fmt;             // 1 = gt_valid int32, 0 = 1-byte bool
__device__ int      g_done;            // completion counter (self-resets each replay)

// ---------------- packed f32x2 helpers ----------------
__device__ __forceinline__ unsigned long long f2pk(float lo, float hi) {
    unsigned long long r;
    asm("mov.b64 %0, {%1,%2};" : "=l"(r) : "f"(lo), "f"(hi));
    return r;
}
__device__ __forceinline__ unsigned long long fma2(unsigned long long a, unsigned long long b,
                                                   unsigned long long c) {
    unsigned long long r;
    asm("fma.rn.f32x2 %0, %1, %2, %3;" : "=l"(r) : "l"(a), "l"(b), "l"(c));
    return r;
}
__device__ __forceinline__ void upk(unsigned long long v, float& lo, float& hi) {
    asm("mov.b64 {%0,%1}, %2;" : "=f"(lo), "=f"(hi) : "l"(v));
}

// ---------------- kernels ----------------
// init min-arrays + counters + detect gt_valid format (any 32-bit word > 1 => byte-bool).
__global__ void k_init(const unsigned* __restrict__ w) {
    int stride = gridDim.x * blockDim.x;
    int i = blockIdx.x * blockDim.x + threadIdx.x;
    for (int k = i; k < BB * NP; k += stride) g_prmin[k] = INF_BITS;
    for (int k = i; k < BB * NG; k += stride) g_gtmin[k] = INF_BITS;
    if (i < BB) g_cnt[i] = 0;
    if (i == 0) { g_fmt = 1; g_done = 0; }
    // detect: safe to read (BB*NG)/4 words under both layouts
    for (int k = i; k < (BB * NG) / 4; k += stride)
        if (w[k] > 1u) g_fmt = 0;
}

// warp-aggregated compaction (each 32-thread warp lies within one batch: NG % 32 == 0)
__global__ void k_compact(const float* __restrict__ gt, const void* __restrict__ valid) {
    int i = blockIdx.x * blockDim.x + threadIdx.x;
    if (i >= BB * NG) return;
    int b = i >> 13;           // / NG
    int g = i & (NG - 1);
    bool v;
    if (g_fmt)
        v = (reinterpret_cast<const int*>(valid)[i] != 0);
    else
        v = (reinterpret_cast<const unsigned char*>(valid)[i] != 0);

    unsigned mask = __ballot_sync(0xffffffffu, v);
    int lane = threadIdx.x & 31;
    int base = 0;
    if (lane == 0 && mask) base = atomicAdd(&g_cnt[b], __popc(mask));
    base = __shfl_sync(0xffffffffu, base, 0);
    if (v) {
        int p = base + __popc(mask & ((1u << lane) - 1u));
        const float* s = gt + (size_t)i * 3;
        float x = s[0], y = s[1], z = s[2];
        g_gt[b][0][p] = x;
        g_gt[b][1][p] = y;
        g_gt[b][2][p] = z;
        g_gtsq[b][p]  = x * x + y * y + z * z;
        g_gtidx[b][p] = g;
    }
}

// Fused bidirectional Chamfer + last-block final reduction.
// blockIdx.y = z in [0, 96): z < 32  -> accuracy, b = z>>3, slice = z&7
//                            z >= 32 -> completeness, b = (z-32)>>4, slice = (z-32)&15
// Tile pair-SoA: s[2k]=(x0,x1,y0,y1), s[2k+1]=(z0,z1,sq0,sq1).
// t = fma2(-2qx,gx, fma2(-2qy,gy, fma2(-2qz,gz, gsq))); result = min(t) + |q|^2.
__global__ void __launch_bounds__(T) k_cd(const float* __restrict__ pr,
                                          float* __restrict__ out) {
    int zz = blockIdx.y;
    bool is_acc = zz < SLA * BB;
    int b, slice;
    if (is_acc) { b = zz >> 3; slice = zz & (SLA - 1); }
    else { int zc = zz - SLA * BB; b = zc >> 4; slice = zc & (PS - 1); }
    int cnt = g_cnt[b];

    __shared__ __align__(16) float4 s[TILE_MAX];  // 16 KB

    int qbase = blockIdx.x * (T * Q);
    bool active;
    int tileLen = 0, t0 = 0;
    if (is_acc) {
        int npad = (cnt + 7) & ~7;
        int L = (((npad + SLA - 1) / SLA) + 7) & ~7;   // slice len, mult of 8, <= 1024
        t0 = slice * L;
        int t1 = min(t0 + L, npad);
        active = (t0 < t1);
        tileLen = active ? (t1 - t0) : 0;
    } else {
        t0 = slice * PSL;
        tileLen = PSL;
        active = (qbase < cnt);
    }

    if (active) {
        if (is_acc) {
            for (int i = threadIdx.x; i < tileLen; i += T) {
                int idx = t0 + i;
                float x, y, z, sq;
                if (idx < cnt) {
                    x = g_gt[b][0][idx]; y = g_gt[b][1][idx]; z = g_gt[b][2][idx];
                    sq = g_gtsq[b][idx];
                } else {  // in-register sentinel (pad region, at most 7 entries)
                    x = 0.f; y = 0.f; z = 0.f; sq = __uint_as_float(INF_BITS);
                }
                float* base = reinterpret_cast<float*>(&s[(i >> 1) * 2]);
                int h = i & 1;
                base[0 + h] = x; base[2 + h] = y; base[4 + h] = z; base[6 + h] = sq;
            }
        } else {
            for (int i = threadIdx.x; i < tileLen; i += T) {
                const float* p = pr + ((size_t)b * NP + t0 + i) * 3;
                float x = p[0], y = p[1], z = p[2];
                float sq = x * x + y * y + z * z;
                float* base = reinterpret_cast<float*>(&s[(i >> 1) * 2]);
                int h = i & 1;
                base[0 + h] = x; base[2 + h] = y; base[4 + h] = z; base[6 + h] = sq;
            }
        }
        __syncthreads();

        unsigned long long q2x[Q], q2y[Q], q2z[Q];
        float qsq[Q], m0[Q], m1[Q];
#pragma unroll
        for (int q = 0; q < Q; q++) {
            int qq = qbase + threadIdx.x + q * T;
            float x, y, z, sq;
            if (is_acc) {
                const float* p = pr + ((size_t)b * NP + qq) * 3;
                x = p[0]; y = p[1]; z = p[2];
                sq = x * x + y * y + z * z;
            } else {
                // qq >= cnt reads stale data; result discarded at the atomic
                x = g_gt[b][0][qq]; y = g_gt[b][1][qq]; z = g_gt[b][2][qq];
                sq = (qq < cnt) ? g_gtsq[b][qq] : 0.f;
            }
            float nx = -2.f * x, ny = -2.f * y, nz = -2.f * z;
            q2x[q] = f2pk(nx, nx); q2y[q] = f2pk(ny, ny); q2z[q] = f2pk(nz, nz);
            qsq[q] = sq;
            m0[q] = __uint_as_float(INF_BITS);
            m1[q] = __uint_as_float(INF_BITS);
        }

        int pairs = tileLen >> 1;
#pragma unroll 4
        for (int k = 0; k < pairs; k++) {
            float4 a  = s[k * 2];
            float4 bv = s[k * 2 + 1];
            unsigned long long gx = f2pk(a.x, a.y);
            unsigned long long gy = f2pk(a.z, a.w);
            unsigned long long gz = f2pk(bv.x, bv.y);
            unsigned long long gs = f2pk(bv.z, bv.w);
#pragma unroll
            for (int q = 0; q < Q; q++) {
                unsigned long long t = fma2(q2x[q], gx, fma2(q2y[q], gy, fma2(q2z[q], gz, gs)));
                float tl, th; upk(t, tl, th);
                m0[q] = fminf(m0[q], tl);
                m1[q] = fminf(m1[q], th);
            }
        }

#pragma unroll
        for (int q = 0; q < Q; q++) {
            int qq = qbase + threadIdx.x + q * T;
            float m = fmaxf(fminf(m0[q], m1[q]) + qsq[q], 0.f);
            if (is_acc) {
                atomicMin(&g_prmin[b * NP + qq], __float_as_uint(m));
            } else if (qq < cnt) {
                int orig = g_gtidx[b][qq];
                atomicMin(&g_gtmin[b * NG + orig], __float_as_uint(m));
            }
        }
    }

    // ---- completion: last block does the final reduction ----
    __shared__ bool isLast;
    __shared__ float sa;
    __shared__ float sc[BB];
    __threadfence();
    __syncthreads();
    if (threadIdx.x == 0) {
        int prev = atomicAdd(&g_done, 1);
        isLast = (prev == NBLK - 1);
        if (isLast) __threadfence();   // acquire all blocks' writes
        sa = 0.f;
    }
    if (threadIdx.x < BB) sc[threadIdx.x] = 0.f;
    __syncthreads();
    if (!isLast) return;

    float la = 0.f;
    for (int i = threadIdx.x; i < BB * NP; i += T)
        la += __uint_as_float(g_prmin[i]);
    atomicAdd(&sa, la);

    for (int bb = 0; bb < BB; bb++) {
        float lc = 0.f;
        for (int i = threadIdx.x; i < NG; i += T) {
            unsigned v = g_gtmin[bb * NG + i];
            if (v != INF_BITS) lc += __uint_as_float(v);  // only valid gt were written
        }
        atomicAdd(&sc[bb], lc);
    }
    __syncthreads();

    if (threadIdx.x == 0) {
        float loss_acc = sa / (float)(BB * NP);
        float loss_com = 0.f;
        for (int bb = 0; bb < BB; bb++)
            loss_com += sc[bb] / fmaxf((float)g_cnt[bb], 1.f);
        loss_com /= (float)BB;
        out[0] = 2.f * (loss_acc + loss_com);  // acc + com + cd, cd = acc + com
        g_done = 0;                            // reset for next graph replay
    }
}

// ---------------- launch ----------------
extern "C" void kernel_launch(void* const* d_in, const int* in_sizes, int n_in,
                              void* d_out, int out_size) {
    const float* pr    = (const float*)d_in[0];  // [B,NP,3] f32
    const float* gt    = (const float*)d_in[1];  // [B,NG,3] f32
    const void*  valid = d_in[2];                // [B,NG] bool(1B) or int32

    k_init<<<256, 256>>>((const unsigned*)valid);
    k_compact<<<(BB * NG + 255) / 256, 256>>>(gt, valid);
    k_cd<<<dim3(GRID_X, GRID_Z), T>>>(pr, (float*)d_out);
}

// round 6
// speedup vs baseline: 1.4775x; 1.0731x over previous
#include <cuda_runtime.h>
#include <stdint.h>

#define BB 4
#define NP 8192
#define NG 8192
#define T  256          // threads per block
#define Q  8            // queries per thread
#define SLA 16          // gt slices (acc direction)  -> L ~ cnt/16 (~256)
#define PS 32           // pred slices (com direction)
#define PSL (NP / PS)   // 256 pred points per slice
#define GRID_X (NP / (T * Q))           // 4
#define GRID_Z (SLA * BB + PS * BB)     // 64 + 128 = 192
#define NBLK (GRID_X * GRID_Z)          // 768 blocks
#define TILE_MAX 512                    // max points per tile (8 KB smem)

#define INF_BITS 0x7F800000u

// ---------------- device scratch (no allocs allowed) ----------------
__device__ float    g_gt[BB][3][NG];   // compacted valid gt, SoA ([cnt,NG) = stale, never used)
__device__ float    g_gtsq[BB][NG];    // |g|^2 per compacted gt
__device__ int      g_gtidx[BB][NG];   // original gt index of compacted entry
__device__ int      g_cnt[BB];
__device__ unsigned g_prmin[BB * NP];  // per-pred min d2 (float bits)
__device__ unsigned g_gtmin[BB * NG];  // per-ORIGINAL-gt min d2 (float bits)
__device__ int      g_fmt;             // 1 = gt_valid int32, 0 = 1-byte bool
__device__ int      g_done;            // completion counter (self-resets each replay)

// ---------------- packed f32x2 helpers ----------------
__device__ __forceinline__ unsigned long long f2pk(float lo, float hi) {
    unsigned long long r;
    asm("mov.b64 %0, {%1,%2};" : "=l"(r) : "f"(lo), "f"(hi));
    return r;
}
__device__ __forceinline__ unsigned long long fma2(unsigned long long a, unsigned long long b,
                                                   unsigned long long c) {
    unsigned long long r;
    asm("fma.rn.f32x2 %0, %1, %2, %3;" : "=l"(r) : "l"(a), "l"(b), "l"(c));
    return r;
}
__device__ __forceinline__ void upk(unsigned long long v, float& lo, float& hi) {
    asm("mov.b64 {%0,%1}, %2;" : "=f"(lo), "=f"(hi) : "l"(v));
}

// ---------------- kernels ----------------
// detect gt_valid format + reset counters (any 32-bit word > 1 => byte-bool).
__global__ void k_init(const unsigned* __restrict__ w) {
    int stride = gridDim.x * blockDim.x;
    int i = blockIdx.x * blockDim.x + threadIdx.x;
    if (i < BB) g_cnt[i] = 0;
    if (i == 0) { g_fmt = 1; g_done = 0; }
    // detect: safe to read (BB*NG)/4 words under both layouts
    for (int k = i; k < (BB * NG) / 4; k += stride)
        if (w[k] > 1u) g_fmt = 0;
}

// warp-aggregated compaction + min-array init (32768 threads; NG % 32 == 0)
__global__ void k_compact(const float* __restrict__ gt, const void* __restrict__ valid) {
    int i = blockIdx.x * blockDim.x + threadIdx.x;
    if (i >= BB * NG) return;
    // reset min arrays (both are BB*NG == BB*NP words): 1 word each per thread
    g_prmin[i] = INF_BITS;
    g_gtmin[i] = INF_BITS;

    int b = i >> 13;           // / NG
    int g = i & (NG - 1);
    bool v;
    if (g_fmt)
        v = (reinterpret_cast<const int*>(valid)[i] != 0);
    else
        v = (reinterpret_cast<const unsigned char*>(valid)[i] != 0);

    unsigned mask = __ballot_sync(0xffffffffu, v);
    int lane = threadIdx.x & 31;
    int base = 0;
    if (lane == 0 && mask) base = atomicAdd(&g_cnt[b], __popc(mask));
    base = __shfl_sync(0xffffffffu, base, 0);
    if (v) {
        int p = base + __popc(mask & ((1u << lane) - 1u));
        const float* s = gt + (size_t)i * 3;
        float x = s[0], y = s[1], z = s[2];
        g_gt[b][0][p] = x;
        g_gt[b][1][p] = y;
        g_gt[b][2][p] = z;
        g_gtsq[b][p]  = x * x + y * y + z * z;
        g_gtidx[b][p] = g;
    }
}

// Fused bidirectional Chamfer + last-block final reduction.
// blockIdx.y = z in [0, 192): z < 64  -> accuracy, b = z>>4, slice = z&15
//                             z >= 64 -> completeness, b = (z-64)>>5, slice = (z-64)&31
// Tile pair-SoA: s[2k]=(x0,x1,y0,y1), s[2k+1]=(z0,z1,sq0,sq1).
// t = fma2(-2qx,gx, fma2(-2qy,gy, fma2(-2qz,gz, gsq))); result = min(t) + |q|^2.
__global__ void __launch_bounds__(T) k_cd(const float* __restrict__ pr,
                                          float* __restrict__ out) {
    int zz = blockIdx.y;
    bool is_acc = zz < SLA * BB;
    int b, slice;
    if (is_acc) { b = zz >> 4; slice = zz & (SLA - 1); }
    else { int zc = zz - SLA * BB; b = zc >> 5; slice = zc & (PS - 1); }
    int cnt = g_cnt[b];

    __shared__ __align__(16) float4 s[TILE_MAX];  // 8 KB

    int qbase = blockIdx.x * (T * Q);
    bool active;
    int tileLen = 0, t0 = 0;
    if (is_acc) {
        int npad = (cnt + 7) & ~7;
        int L = (((npad + SLA - 1) / SLA) + 7) & ~7;   // slice len, mult of 8, <= 512
        t0 = slice * L;
        int t1 = min(t0 + L, npad);
        active = (t0 < t1);
        tileLen = active ? (t1 - t0) : 0;
    } else {
        t0 = slice * PSL;
        tileLen = PSL;
        active = (qbase < cnt);
    }

    if (active) {
        if (is_acc) {
            for (int i = threadIdx.x; i < tileLen; i += T) {
                int idx = t0 + i;
                float x, y, z, sq;
                if (idx < cnt) {
                    x = g_gt[b][0][idx]; y = g_gt[b][1][idx]; z = g_gt[b][2][idx];
                    sq = g_gtsq[b][idx];
                } else {  // in-register sentinel (pad region, at most 7 entries)
                    x = 0.f; y = 0.f; z = 0.f; sq = __uint_as_float(INF_BITS);
                }
                float* base = reinterpret_cast<float*>(&s[(i >> 1) * 2]);
                int h = i & 1;
                base[0 + h] = x; base[2 + h] = y; base[4 + h] = z; base[6 + h] = sq;
            }
        } else {
            for (int i = threadIdx.x; i < tileLen; i += T) {
                const float* p = pr + ((size_t)b * NP + t0 + i) * 3;
                float x = p[0], y = p[1], z = p[2];
                float sq = x * x + y * y + z * z;
                float* base = reinterpret_cast<float*>(&s[(i >> 1) * 2]);
                int h = i & 1;
                base[0 + h] = x; base[2 + h] = y; base[4 + h] = z; base[6 + h] = sq;
            }
        }
        __syncthreads();

        unsigned long long q2x[Q], q2y[Q], q2z[Q];
        float qsq[Q], m0[Q], m1[Q];
#pragma unroll
        for (int q = 0; q < Q; q++) {
            int qq = qbase + threadIdx.x + q * T;
            float x, y, z, sq;
            if (is_acc) {
                const float* p = pr + ((size_t)b * NP + qq) * 3;
                x = p[0]; y = p[1]; z = p[2];
                sq = x * x + y * y + z * z;
            } else {
                // qq >= cnt reads stale data; result discarded at the atomic
                x = g_gt[b][0][qq]; y = g_gt[b][1][qq]; z = g_gt[b][2][qq];
                sq = (qq < cnt) ? g_gtsq[b][qq] : 0.f;
            }
            float nx = -2.f * x, ny = -2.f * y, nz = -2.f * z;
            q2x[q] = f2pk(nx, nx); q2y[q] = f2pk(ny, ny); q2z[q] = f2pk(nz, nz);
            qsq[q] = sq;
            m0[q] = __uint_as_float(INF_BITS);
            m1[q] = __uint_as_float(INF_BITS);
        }

        int pairs = tileLen >> 1;
#pragma unroll 2
        for (int k = 0; k < pairs; k++) {
            float4 a  = s[k * 2];
            float4 bv = s[k * 2 + 1];
            unsigned long long gx = f2pk(a.x, a.y);
            unsigned long long gy = f2pk(a.z, a.w);
            unsigned long long gz = f2pk(bv.x, bv.y);
            unsigned long long gs = f2pk(bv.z, bv.w);
#pragma unroll
            for (int q = 0; q < Q; q++) {
                unsigned long long t = fma2(q2x[q], gx, fma2(q2y[q], gy, fma2(q2z[q], gz, gs)));
                float tl, th; upk(t, tl, th);
                m0[q] = fminf(m0[q], tl);
                m1[q] = fminf(m1[q], th);
            }
        }

#pragma unroll
        for (int q = 0; q < Q; q++) {
            int qq = qbase + threadIdx.x + q * T;
            float m = fmaxf(fminf(m0[q], m1[q]) + qsq[q], 0.f);
            if (is_acc) {
                atomicMin(&g_prmin[b * NP + qq], __float_as_uint(m));
            } else if (qq < cnt) {
                int orig = g_gtidx[b][qq];
                atomicMin(&g_gtmin[b * NG + orig], __float_as_uint(m));
            }
        }
    }

    // ---- completion: last block does the final reduction ----
    __shared__ bool isLast;
    __shared__ float sa;
    __shared__ float sc[BB];
    __threadfence();
    __syncthreads();
    if (threadIdx.x == 0) {
        int prev = atomicAdd(&g_done, 1);
        isLast = (prev == NBLK - 1);
        if (isLast) __threadfence();   // acquire all blocks' writes
        sa = 0.f;
    }
    if (threadIdx.x < BB) sc[threadIdx.x] = 0.f;
    __syncthreads();
    if (!isLast) return;

    float la = 0.f;
    for (int i = threadIdx.x; i < BB * NP; i += T)
        la += __uint_as_float(g_prmin[i]);
    atomicAdd(&sa, la);

    for (int bb = 0; bb < BB; bb++) {
        float lc = 0.f;
        for (int i = threadIdx.x; i < NG; i += T) {
            unsigned v = g_gtmin[bb * NG + i];
            if (v != INF_BITS) lc += __uint_as_float(v);  // only valid gt were written
        }
        atomicAdd(&sc[bb], lc);
    }
    __syncthreads();

    if (threadIdx.x == 0) {
        float loss_acc = sa / (float)(BB * NP);
        float loss_com = 0.f;
        for (int bb = 0; bb < BB; bb++)
            loss_com += sc[bb] / fmaxf((float)g_cnt[bb], 1.f);
        loss_com /= (float)BB;
        out[0] = 2.f * (loss_acc + loss_com);  // acc + com + cd, cd = acc + com
        g_done = 0;                            // reset for next graph replay
    }
}

// ---------------- launch ----------------
extern "C" void kernel_launch(void* const* d_in, const int* in_sizes, int n_in,
                              void* d_out, int out_size) {
    const float* pr    = (const float*)d_in[0];  // [B,NP,3] f32
    const float* gt    = (const float*)d_in[1];  // [B,NG,3] f32
    const void*  valid = d_in[2];                // [B,NG] bool(1B) or int32

    k_init<<<64, 256>>>((const unsigned*)valid);
    k_compact<<<(BB * NG + 255) / 256, 256>>>(gt, valid);
    k_cd<<<dim3(GRID_X, GRID_Z), T>>>(pr, (float*)d_out);
}